// round 14
// baseline (speedup 1.0000x reference)
#include <cuda_runtime.h>
#include <cuda_fp16.h>

// out[e] = dot(h[src[e]], h[dst[e]]), D_FEAT=128 fp32, int32 indices.
//
// pass 1: convert h -> fp16 table (25.6MB), 8 floats/thread.
// pass 2: fp16 gather, 16 edges/warp via 8 groups x 4 lanes. Group q
//         handles edges eb+q and eb+8+q. Per lane: 16 independent LDG.128.
//         Width-4 shuffle reduce (6 shfl/warp vs 12), all 16 scores
//         assembled into lanes 0..15 -> one coalesced 64B store.
// rel_err 3.9e-4 (identical depth-2 fp16 accumulation as measured).

#define D_FEAT    128
#define MAX_NODES 131072

__device__ __half g_h16[(size_t)MAX_NODES * D_FEAT];   // 33.5MB scratch

// ---------------- pass 1: fp32 -> fp16 table ----------------

__device__ __forceinline__ unsigned int pack_h2(float x, float y) {
    __half2 p = __floats2half2_rn(x, y);
    return *reinterpret_cast<unsigned int*>(&p);
}

__global__ void __launch_bounds__(256)
convert_kernel(const float* __restrict__ h, int n_chunks /* = n_floats/8 */)
{
    int i = blockIdx.x * blockDim.x + threadIdx.x;
    if (i >= n_chunks) return;
    const float4* h4 = reinterpret_cast<const float4*>(h);
    float4 f0 = __ldg(&h4[2 * i]);
    float4 f1 = __ldg(&h4[2 * i + 1]);
    uint4 p;
    p.x = pack_h2(f0.x, f0.y);
    p.y = pack_h2(f0.z, f0.w);
    p.z = pack_h2(f1.x, f1.y);
    p.w = pack_h2(f1.z, f1.w);
    reinterpret_cast<uint4*>(g_h16)[i] = p;
}

// ---------------- pass 2: fp16 gather + dot ----------------

__device__ __forceinline__ __half2 u2h2(unsigned int u) {
    return *reinterpret_cast<__half2*>(&u);
}

// depth-2 fp16 accumulation of two chunk-pairs, then fp32 horizontal sum.
__device__ __forceinline__ float h16_dot_pair(uint4 a0, uint4 a1,
                                              uint4 b0, uint4 b1)
{
    __half2 c0 = __hmul2(u2h2(a0.x), u2h2(b0.x));
    __half2 c1 = __hmul2(u2h2(a0.y), u2h2(b0.y));
    __half2 c2 = __hmul2(u2h2(a0.z), u2h2(b0.z));
    __half2 c3 = __hmul2(u2h2(a0.w), u2h2(b0.w));
    c0 = __hfma2(u2h2(a1.x), u2h2(b1.x), c0);
    c1 = __hfma2(u2h2(a1.y), u2h2(b1.y), c1);
    c2 = __hfma2(u2h2(a1.z), u2h2(b1.z), c2);
    c3 = __hfma2(u2h2(a1.w), u2h2(b1.w), c3);

    float2 f0 = __half22float2(c0);
    float2 f1 = __half22float2(c1);
    float2 f2 = __half22float2(c2);
    float2 f3 = __half22float2(c3);

    return ((f0.x + f0.y) + (f1.x + f1.y)) +
           ((f2.x + f2.y) + (f3.x + f3.y));
}

// 4-lane-group edge dot: lane t of the group loads chunks t, t+4, t+8, t+12
// of each 16-uint4 row. Depth-2 pairing preserved.
__device__ __forceinline__ float h16_edge_dot4(int s, int d, int t)
{
    const uint4* ps = reinterpret_cast<const uint4*>(g_h16 + (size_t)s * D_FEAT);
    const uint4* pd = reinterpret_cast<const uint4*>(g_h16 + (size_t)d * D_FEAT);
    uint4 a0 = __ldg(&ps[t]);
    uint4 a1 = __ldg(&ps[t +  4]);
    uint4 a2 = __ldg(&ps[t +  8]);
    uint4 a3 = __ldg(&ps[t + 12]);
    uint4 b0 = __ldg(&pd[t]);
    uint4 b1 = __ldg(&pd[t +  4]);
    uint4 b2 = __ldg(&pd[t +  8]);
    uint4 b3 = __ldg(&pd[t + 12]);
    return h16_dot_pair(a0, a1, b0, b1) + h16_dot_pair(a2, a3, b2, b3);
}

// Guard-free: n_edges % 128 == 0.
__global__ void __launch_bounds__(256)
edge_dot_h16_exact(const int* __restrict__ src,
                   const int* __restrict__ dst,
                   float* __restrict__ out)
{
    int warp = (int)((blockIdx.x * 256u + threadIdx.x) >> 5);
    int lane = threadIdx.x & 31;
    int q    = lane >> 2;        // group 0..7
    int t    = lane & 3;         // lane within group

    int eb = warp * 16;          // warp's edges: eb .. eb+15

    // broadcast scalar index loads (4 lanes/group share an address)
    int sA = __ldg(&src[eb + q]);
    int dA = __ldg(&dst[eb + q]);
    int sB = __ldg(&src[eb + 8 + q]);
    int dB = __ldg(&dst[eb + 8 + q]);

    float accA = h16_edge_dot4(sA, dA, t);
    float accB = h16_edge_dot4(sB, dB, t);

    // width-4 reductions
    accA += __shfl_down_sync(0xFFFFFFFFu, accA, 2, 4);
    accB += __shfl_down_sync(0xFFFFFFFFu, accB, 2, 4);
    accA += __shfl_down_sync(0xFFFFFFFFu, accA, 1, 4);
    accB += __shfl_down_sync(0xFFFFFFFFu, accB, 1, 4);

    // assemble: lane l<8 gets accA(group l); lanes 8..15 get accB(group l-8)
    float resA = __shfl_sync(0xFFFFFFFFu, accA, (lane & 7) << 2);
    float resB = __shfl_sync(0xFFFFFFFFu, accB, (lane & 7) << 2);

    if (lane < 16)
        out[eb + lane] = (lane < 8) ? resA : resB;  // one 64B coalesced STG
}

// Guarded general version (8-lane groups, 2 edges/group — proven R10 shape).
__device__ __forceinline__ float h16_edge_dot8(int s, int d, int sub)
{
    const uint4* hs = reinterpret_cast<const uint4*>(g_h16 + (size_t)s * D_FEAT);
    const uint4* hd = reinterpret_cast<const uint4*>(g_h16 + (size_t)d * D_FEAT);
    uint4 a0 = __ldg(&hs[sub]);
    uint4 a1 = __ldg(&hs[sub + 8]);
    uint4 b0 = __ldg(&hd[sub]);
    uint4 b1 = __ldg(&hd[sub + 8]);
    return h16_dot_pair(a0, a1, b0, b1);
}

__global__ void __launch_bounds__(256)
edge_dot_h16_guarded(const int* __restrict__ src,
                     const int* __restrict__ dst,
                     float* __restrict__ out,
                     int n_edges)
{
    int warp = (int)((blockIdx.x * 256u + threadIdx.x) >> 5);
    int lane = threadIdx.x & 31;
    int grp  = lane >> 3;
    int sub  = lane & 7;

    int e0 = warp * 8 + grp;
    int e1 = e0 + 4;
    if (e0 >= n_edges) return;
    bool do1 = (e1 < n_edges);

    int s0 = __ldg(&src[e0]);
    int d0 = __ldg(&dst[e0]);
    int s1 = do1 ? __ldg(&src[e1]) : s0;
    int d1 = do1 ? __ldg(&dst[e1]) : d0;

    float accA = h16_edge_dot8(s0, d0, sub);
    float accB = h16_edge_dot8(s1, d1, sub);

    accA += __shfl_down_sync(0xFFFFFFFFu, accA, 4, 8);
    accB += __shfl_down_sync(0xFFFFFFFFu, accB, 4, 8);
    accA += __shfl_down_sync(0xFFFFFFFFu, accA, 2, 8);
    accB += __shfl_down_sync(0xFFFFFFFFu, accB, 2, 8);
    accA += __shfl_down_sync(0xFFFFFFFFu, accA, 1, 8);
    accB += __shfl_down_sync(0xFFFFFFFFu, accB, 1, 8);

    if (sub == 0) {
        out[e0] = accA;
        if (do1) out[e1] = accB;
    }
}

// ---------------- fallback: proven fp32 kernel (R3) ----------------

__device__ __forceinline__ float dot4(float4 a, float4 b) {
    float acc = a.x * b.x;
    acc = fmaf(a.y, b.y, acc);
    acc = fmaf(a.z, b.z, acc);
    acc = fmaf(a.w, b.w, acc);
    return acc;
}

__global__ void __launch_bounds__(256)
edge_dot_simple(const float* __restrict__ h,
                const int* __restrict__ src,
                const int* __restrict__ dst,
                float* __restrict__ out,
                int n_edges)
{
    int warp = (int)((blockIdx.x * 256u + threadIdx.x) >> 5);
    int lane = threadIdx.x & 31;
    int grp  = lane >> 3;
    int sub  = lane & 7;

    int e = warp * 4 + grp;
    if (e >= n_edges) return;

    int s = __ldg(&src[e]);
    int d = __ldg(&dst[e]);

    const float4* hs = reinterpret_cast<const float4*>(h + (long long)s * D_FEAT);
    const float4* hd = reinterpret_cast<const float4*>(h + (long long)d * D_FEAT);

    float4 a0 = __ldg(&hs[sub]);
    float4 a1 = __ldg(&hs[sub +  8]);
    float4 a2 = __ldg(&hs[sub + 16]);
    float4 a3 = __ldg(&hs[sub + 24]);
    float4 b0 = __ldg(&hd[sub]);
    float4 b1 = __ldg(&hd[sub +  8]);
    float4 b2 = __ldg(&hd[sub + 16]);
    float4 b3 = __ldg(&hd[sub + 24]);

    float acc = (dot4(a0, b0) + dot4(a1, b1)) +
                (dot4(a2, b2) + dot4(a3, b3));

    acc += __shfl_down_sync(0xFFFFFFFFu, acc, 4, 8);
    acc += __shfl_down_sync(0xFFFFFFFFu, acc, 2, 8);
    acc += __shfl_down_sync(0xFFFFFFFFu, acc, 1, 8);

    if (sub == 0)
        out[e] = acc;
}

// ---------------- launch ----------------

extern "C" void kernel_launch(void* const* d_in, const int* in_sizes, int n_in,
                              void* d_out, int out_size)
{
    const float* h   = (const float*)d_in[0];
    const int*   src = (const int*)d_in[1];
    const int*   dst = (const int*)d_in[2];
    float*       out = (float*)d_out;

    int n_edges      = in_sizes[1];
    int n_feat_total = in_sizes[0];          // total floats in h
    int n_nodes      = n_feat_total / D_FEAT;

    if (n_nodes > MAX_NODES || (n_feat_total & 7) != 0) {
        edge_dot_simple<<<(n_edges + 31) / 32, 256>>>(h, src, dst, out, n_edges);
        return;
    }

    int n_chunks = n_feat_total / 8;   // 8 floats -> 8 halves per thread
    convert_kernel<<<(n_chunks + 255) / 256, 256>>>(h, n_chunks);

    if ((n_edges & 127) == 0) {
        // 16 edges/warp, 128 edges/block, 4-lane groups, guard-free
        edge_dot_h16_exact<<<n_edges / 128, 256>>>(src, dst, out);
    } else {
        edge_dot_h16_guarded<<<(n_edges + 63) / 64, 256>>>(src, dst, out, n_edges);
    }
}

// round 15
// speedup vs baseline: 1.0417x; 1.0417x over previous
#include <cuda_runtime.h>
#include <cuda_fp16.h>

// out[e] = dot(h[src[e]], h[dst[e]]), D_FEAT=128 fp32, int32 indices.
//
// Proven-best pipeline (R13 shape):
// pass 1: convert h -> fp16 table (25.6MB), 8 floats/thread, __ldcs reads
//         (fp32 source is dead after this — keep it out of L2 so the fp16
//         table stays resident for the gather).
// pass 2: fp16 gather, 16 edges/warp via 4 groups x 8 lanes, 4 consecutive
//         edges per group. Indices via broadcast int4 loads; 128B contiguous
//         per row per LDG.128 (L1-wavefront-optimal — 64B/4-lane variant
//         measured worse); scores stored as one STG.128 per group.
// rel_err 3.9e-4 (gate 1e-3), depth-2 fp16 accumulation then fp32.

#define D_FEAT    128
#define MAX_NODES 131072

__device__ __half g_h16[(size_t)MAX_NODES * D_FEAT];   // 33.5MB scratch

// ---------------- pass 1: fp32 -> fp16 table ----------------

__device__ __forceinline__ unsigned int pack_h2(float x, float y) {
    __half2 p = __floats2half2_rn(x, y);
    return *reinterpret_cast<unsigned int*>(&p);
}

__global__ void __launch_bounds__(512)
convert_kernel(const float* __restrict__ h, int n_chunks /* = n_floats/8 */)
{
    int i = blockIdx.x * blockDim.x + threadIdx.x;
    if (i >= n_chunks) return;
    const float4* h4 = reinterpret_cast<const float4*>(h);
    float4 f0 = __ldcs(&h4[2 * i]);       // streaming: evict-first
    float4 f1 = __ldcs(&h4[2 * i + 1]);
    uint4 p;
    p.x = pack_h2(f0.x, f0.y);
    p.y = pack_h2(f0.z, f0.w);
    p.z = pack_h2(f1.x, f1.y);
    p.w = pack_h2(f1.z, f1.w);
    reinterpret_cast<uint4*>(g_h16)[i] = p;
}

// ---------------- pass 2: fp16 gather + dot ----------------

__device__ __forceinline__ __half2 u2h2(unsigned int u) {
    return *reinterpret_cast<__half2*>(&u);
}

__device__ __forceinline__ float h16_dot_pair(uint4 a0, uint4 a1,
                                              uint4 b0, uint4 b1)
{
    __half2 c0 = __hmul2(u2h2(a0.x), u2h2(b0.x));
    __half2 c1 = __hmul2(u2h2(a0.y), u2h2(b0.y));
    __half2 c2 = __hmul2(u2h2(a0.z), u2h2(b0.z));
    __half2 c3 = __hmul2(u2h2(a0.w), u2h2(b0.w));
    c0 = __hfma2(u2h2(a1.x), u2h2(b1.x), c0);
    c1 = __hfma2(u2h2(a1.y), u2h2(b1.y), c1);
    c2 = __hfma2(u2h2(a1.z), u2h2(b1.z), c2);
    c3 = __hfma2(u2h2(a1.w), u2h2(b1.w), c3);

    float2 f0 = __half22float2(c0);
    float2 f1 = __half22float2(c1);
    float2 f2 = __half22float2(c2);
    float2 f3 = __half22float2(c3);

    return ((f0.x + f0.y) + (f1.x + f1.y)) +
           ((f2.x + f2.y) + (f3.x + f3.y));
}

__device__ __forceinline__ float h16_edge_dot(int s, int d, int sub)
{
    const uint4* hs = reinterpret_cast<const uint4*>(g_h16 + (size_t)s * D_FEAT);
    const uint4* hd = reinterpret_cast<const uint4*>(g_h16 + (size_t)d * D_FEAT);
    uint4 a0 = __ldg(&hs[sub]);
    uint4 a1 = __ldg(&hs[sub + 8]);
    uint4 b0 = __ldg(&hd[sub]);
    uint4 b1 = __ldg(&hd[sub + 8]);
    return h16_dot_pair(a0, a1, b0, b1);
}

// Guard-free: n_edges % 128 == 0. Each 8-lane group: 4 consecutive edges.
__global__ void __launch_bounds__(256)
edge_dot_h16_exact(const int* __restrict__ src,
                   const int* __restrict__ dst,
                   float* __restrict__ out)
{
    int warp = (int)((blockIdx.x * 256u + threadIdx.x) >> 5);
    int lane = threadIdx.x & 31;
    int grp  = lane >> 3;
    int sub  = lane & 7;

    int eb = warp * 16 + grp * 4;   // group's edges: eb .. eb+3

    // broadcast vector index loads (all 8 lanes same address -> 1 wavefront)
    int4 sv = __ldg(reinterpret_cast<const int4*>(src + eb));
    int4 dv = __ldg(reinterpret_cast<const int4*>(dst + eb));

    float accA = h16_edge_dot(sv.x, dv.x, sub);
    float accB = h16_edge_dot(sv.y, dv.y, sub);
    float accC = h16_edge_dot(sv.z, dv.z, sub);
    float accD = h16_edge_dot(sv.w, dv.w, sub);

    accA += __shfl_down_sync(0xFFFFFFFFu, accA, 4, 8);
    accB += __shfl_down_sync(0xFFFFFFFFu, accB, 4, 8);
    accC += __shfl_down_sync(0xFFFFFFFFu, accC, 4, 8);
    accD += __shfl_down_sync(0xFFFFFFFFu, accD, 4, 8);
    accA += __shfl_down_sync(0xFFFFFFFFu, accA, 2, 8);
    accB += __shfl_down_sync(0xFFFFFFFFu, accB, 2, 8);
    accC += __shfl_down_sync(0xFFFFFFFFu, accC, 2, 8);
    accD += __shfl_down_sync(0xFFFFFFFFu, accD, 2, 8);
    accA += __shfl_down_sync(0xFFFFFFFFu, accA, 1, 8);
    accB += __shfl_down_sync(0xFFFFFFFFu, accB, 1, 8);
    accC += __shfl_down_sync(0xFFFFFFFFu, accC, 1, 8);
    accD += __shfl_down_sync(0xFFFFFFFFu, accD, 1, 8);

    if (sub == 0) {
        float4 r = make_float4(accA, accB, accC, accD);
        *reinterpret_cast<float4*>(out + eb) = r;   // one STG.128
    }
}

// Guarded general version (2 edges/group, proven R10 shape).
__global__ void __launch_bounds__(256)
edge_dot_h16_guarded(const int* __restrict__ src,
                     const int* __restrict__ dst,
                     float* __restrict__ out,
                     int n_edges)
{
    int warp = (int)((blockIdx.x * 256u + threadIdx.x) >> 5);
    int lane = threadIdx.x & 31;
    int grp  = lane >> 3;
    int sub  = lane & 7;

    int e0 = warp * 8 + grp;
    int e1 = e0 + 4;
    if (e0 >= n_edges) return;
    bool do1 = (e1 < n_edges);

    int s0 = __ldg(&src[e0]);
    int d0 = __ldg(&dst[e0]);
    int s1 = do1 ? __ldg(&src[e1]) : s0;
    int d1 = do1 ? __ldg(&dst[e1]) : d0;

    float accA = h16_edge_dot(s0, d0, sub);
    float accB = h16_edge_dot(s1, d1, sub);

    accA += __shfl_down_sync(0xFFFFFFFFu, accA, 4, 8);
    accB += __shfl_down_sync(0xFFFFFFFFu, accB, 4, 8);
    accA += __shfl_down_sync(0xFFFFFFFFu, accA, 2, 8);
    accB += __shfl_down_sync(0xFFFFFFFFu, accB, 2, 8);
    accA += __shfl_down_sync(0xFFFFFFFFu, accA, 1, 8);
    accB += __shfl_down_sync(0xFFFFFFFFu, accB, 1, 8);

    if (sub == 0) {
        out[e0] = accA;
        if (do1) out[e1] = accB;
    }
}

// ---------------- fallback: proven fp32 kernel (R3) ----------------

__device__ __forceinline__ float dot4(float4 a, float4 b) {
    float acc = a.x * b.x;
    acc = fmaf(a.y, b.y, acc);
    acc = fmaf(a.z, b.z, acc);
    acc = fmaf(a.w, b.w, acc);
    return acc;
}

__global__ void __launch_bounds__(256)
edge_dot_simple(const float* __restrict__ h,
                const int* __restrict__ src,
                const int* __restrict__ dst,
                float* __restrict__ out,
                int n_edges)
{
    int warp = (int)((blockIdx.x * 256u + threadIdx.x) >> 5);
    int lane = threadIdx.x & 31;
    int grp  = lane >> 3;
    int sub  = lane & 7;

    int e = warp * 4 + grp;
    if (e >= n_edges) return;

    int s = __ldg(&src[e]);
    int d = __ldg(&dst[e]);

    const float4* hs = reinterpret_cast<const float4*>(h + (long long)s * D_FEAT);
    const float4* hd = reinterpret_cast<const float4*>(h + (long long)d * D_FEAT);

    float4 a0 = __ldg(&hs[sub]);
    float4 a1 = __ldg(&hs[sub +  8]);
    float4 a2 = __ldg(&hs[sub + 16]);
    float4 a3 = __ldg(&hs[sub + 24]);
    float4 b0 = __ldg(&hd[sub]);
    float4 b1 = __ldg(&hd[sub +  8]);
    float4 b2 = __ldg(&hd[sub + 16]);
    float4 b3 = __ldg(&hd[sub + 24]);

    float acc = (dot4(a0, b0) + dot4(a1, b1)) +
                (dot4(a2, b2) + dot4(a3, b3));

    acc += __shfl_down_sync(0xFFFFFFFFu, acc, 4, 8);
    acc += __shfl_down_sync(0xFFFFFFFFu, acc, 2, 8);
    acc += __shfl_down_sync(0xFFFFFFFFu, acc, 1, 8);

    if (sub == 0)
        out[e] = acc;
}

// ---------------- launch ----------------

extern "C" void kernel_launch(void* const* d_in, const int* in_sizes, int n_in,
                              void* d_out, int out_size)
{
    const float* h   = (const float*)d_in[0];
    const int*   src = (const int*)d_in[1];
    const int*   dst = (const int*)d_in[2];
    float*       out = (float*)d_out;

    int n_edges      = in_sizes[1];
    int n_feat_total = in_sizes[0];          // total floats in h
    int n_nodes      = n_feat_total / D_FEAT;

    if (n_nodes > MAX_NODES || (n_feat_total & 7) != 0) {
        edge_dot_simple<<<(n_edges + 31) / 32, 256>>>(h, src, dst, out, n_edges);
        return;
    }

    int n_chunks = n_feat_total / 8;   // 8 floats -> 8 halves per thread
    convert_kernel<<<(n_chunks + 511) / 512, 512>>>(h, n_chunks);

    if ((n_edges & 127) == 0) {
        // 16 edges/warp, 128 edges/block, 8-lane groups, guard-free
        edge_dot_h16_exact<<<n_edges / 128, 256>>>(src, dst, out);
    } else {
        edge_dot_h16_guarded<<<(n_edges + 63) / 64, 256>>>(src, dst, out, n_edges);
    }
}

// round 16
// speedup vs baseline: 1.1239x; 1.0789x over previous
#include <cuda_runtime.h>
#include <cuda_fp16.h>

// out[e] = dot(h[src[e]], h[dst[e]]), D_FEAT=128 fp32, int32 indices.
//
// Proven-best pipeline (R13, 29.2us):
// pass 1: convert h -> fp16 table (25.6MB), 8 floats/thread via __ldg,
//         256-thread blocks. (Measured: __ldcs / 512-thread variant is
//         ~2us slower — evict-first hurts the paired-vector read pattern.)
// pass 2: fp16 gather, 16 edges/warp via 4 groups x 8 lanes, 4 consecutive
//         edges per group. Indices via broadcast int4 loads; 128B contiguous
//         per row per LDG.128 (L1-wavefront-optimal; 64B/4-lane variant
//         measured worse); scores stored as one STG.128 per group.
// rel_err 3.9e-4 (gate 1e-3), depth-2 fp16 accumulation then fp32.
// Gather is pinned at ~14.3 TB/s effective across all measured variants —
// this is the composed floor for this workload on sm_103a.

#define D_FEAT    128
#define MAX_NODES 131072

__device__ __half g_h16[(size_t)MAX_NODES * D_FEAT];   // 33.5MB scratch

// ---------------- pass 1: fp32 -> fp16 table ----------------

__device__ __forceinline__ unsigned int pack_h2(float x, float y) {
    __half2 p = __floats2half2_rn(x, y);
    return *reinterpret_cast<unsigned int*>(&p);
}

__global__ void __launch_bounds__(256)
convert_kernel(const float* __restrict__ h, int n_chunks /* = n_floats/8 */)
{
    int i = blockIdx.x * blockDim.x + threadIdx.x;
    if (i >= n_chunks) return;
    const float4* h4 = reinterpret_cast<const float4*>(h);
    float4 f0 = __ldg(&h4[2 * i]);
    float4 f1 = __ldg(&h4[2 * i + 1]);
    uint4 p;
    p.x = pack_h2(f0.x, f0.y);
    p.y = pack_h2(f0.z, f0.w);
    p.z = pack_h2(f1.x, f1.y);
    p.w = pack_h2(f1.z, f1.w);
    reinterpret_cast<uint4*>(g_h16)[i] = p;
}

// ---------------- pass 2: fp16 gather + dot ----------------

__device__ __forceinline__ __half2 u2h2(unsigned int u) {
    return *reinterpret_cast<__half2*>(&u);
}

__device__ __forceinline__ float h16_dot_pair(uint4 a0, uint4 a1,
                                              uint4 b0, uint4 b1)
{
    __half2 c0 = __hmul2(u2h2(a0.x), u2h2(b0.x));
    __half2 c1 = __hmul2(u2h2(a0.y), u2h2(b0.y));
    __half2 c2 = __hmul2(u2h2(a0.z), u2h2(b0.z));
    __half2 c3 = __hmul2(u2h2(a0.w), u2h2(b0.w));
    c0 = __hfma2(u2h2(a1.x), u2h2(b1.x), c0);
    c1 = __hfma2(u2h2(a1.y), u2h2(b1.y), c1);
    c2 = __hfma2(u2h2(a1.z), u2h2(b1.z), c2);
    c3 = __hfma2(u2h2(a1.w), u2h2(b1.w), c3);

    float2 f0 = __half22float2(c0);
    float2 f1 = __half22float2(c1);
    float2 f2 = __half22float2(c2);
    float2 f3 = __half22float2(c3);

    return ((f0.x + f0.y) + (f1.x + f1.y)) +
           ((f2.x + f2.y) + (f3.x + f3.y));
}

__device__ __forceinline__ float h16_edge_dot(int s, int d, int sub)
{
    const uint4* hs = reinterpret_cast<const uint4*>(g_h16 + (size_t)s * D_FEAT);
    const uint4* hd = reinterpret_cast<const uint4*>(g_h16 + (size_t)d * D_FEAT);
    uint4 a0 = __ldg(&hs[sub]);
    uint4 a1 = __ldg(&hs[sub + 8]);
    uint4 b0 = __ldg(&hd[sub]);
    uint4 b1 = __ldg(&hd[sub + 8]);
    return h16_dot_pair(a0, a1, b0, b1);
}

// Guard-free: n_edges % 128 == 0. Each 8-lane group: 4 consecutive edges.
__global__ void __launch_bounds__(256)
edge_dot_h16_exact(const int* __restrict__ src,
                   const int* __restrict__ dst,
                   float* __restrict__ out)
{
    int warp = (int)((blockIdx.x * 256u + threadIdx.x) >> 5);
    int lane = threadIdx.x & 31;
    int grp  = lane >> 3;
    int sub  = lane & 7;

    int eb = warp * 16 + grp * 4;   // group's edges: eb .. eb+3

    // broadcast vector index loads (all 8 lanes same address -> 1 wavefront)
    int4 sv = __ldg(reinterpret_cast<const int4*>(src + eb));
    int4 dv = __ldg(reinterpret_cast<const int4*>(dst + eb));

    float accA = h16_edge_dot(sv.x, dv.x, sub);
    float accB = h16_edge_dot(sv.y, dv.y, sub);
    float accC = h16_edge_dot(sv.z, dv.z, sub);
    float accD = h16_edge_dot(sv.w, dv.w, sub);

    accA += __shfl_down_sync(0xFFFFFFFFu, accA, 4, 8);
    accB += __shfl_down_sync(0xFFFFFFFFu, accB, 4, 8);
    accC += __shfl_down_sync(0xFFFFFFFFu, accC, 4, 8);
    accD += __shfl_down_sync(0xFFFFFFFFu, accD, 4, 8);
    accA += __shfl_down_sync(0xFFFFFFFFu, accA, 2, 8);
    accB += __shfl_down_sync(0xFFFFFFFFu, accB, 2, 8);
    accC += __shfl_down_sync(0xFFFFFFFFu, accC, 2, 8);
    accD += __shfl_down_sync(0xFFFFFFFFu, accD, 2, 8);
    accA += __shfl_down_sync(0xFFFFFFFFu, accA, 1, 8);
    accB += __shfl_down_sync(0xFFFFFFFFu, accB, 1, 8);
    accC += __shfl_down_sync(0xFFFFFFFFu, accC, 1, 8);
    accD += __shfl_down_sync(0xFFFFFFFFu, accD, 1, 8);

    if (sub == 0) {
        float4 r = make_float4(accA, accB, accC, accD);
        *reinterpret_cast<float4*>(out + eb) = r;   // one STG.128
    }
}

// Guarded general version (2 edges/group, proven R10 shape).
__global__ void __launch_bounds__(256)
edge_dot_h16_guarded(const int* __restrict__ src,
                     const int* __restrict__ dst,
                     float* __restrict__ out,
                     int n_edges)
{
    int warp = (int)((blockIdx.x * 256u + threadIdx.x) >> 5);
    int lane = threadIdx.x & 31;
    int grp  = lane >> 3;
    int sub  = lane & 7;

    int e0 = warp * 8 + grp;
    int e1 = e0 + 4;
    if (e0 >= n_edges) return;
    bool do1 = (e1 < n_edges);

    int s0 = __ldg(&src[e0]);
    int d0 = __ldg(&dst[e0]);
    int s1 = do1 ? __ldg(&src[e1]) : s0;
    int d1 = do1 ? __ldg(&dst[e1]) : d0;

    float accA = h16_edge_dot(s0, d0, sub);
    float accB = h16_edge_dot(s1, d1, sub);

    accA += __shfl_down_sync(0xFFFFFFFFu, accA, 4, 8);
    accB += __shfl_down_sync(0xFFFFFFFFu, accB, 4, 8);
    accA += __shfl_down_sync(0xFFFFFFFFu, accA, 2, 8);
    accB += __shfl_down_sync(0xFFFFFFFFu, accB, 2, 8);
    accA += __shfl_down_sync(0xFFFFFFFFu, accA, 1, 8);
    accB += __shfl_down_sync(0xFFFFFFFFu, accB, 1, 8);

    if (sub == 0) {
        out[e0] = accA;
        if (do1) out[e1] = accB;
    }
}

// ---------------- fallback: proven fp32 kernel (R3) ----------------

__device__ __forceinline__ float dot4(float4 a, float4 b) {
    float acc = a.x * b.x;
    acc = fmaf(a.y, b.y, acc);
    acc = fmaf(a.z, b.z, acc);
    acc = fmaf(a.w, b.w, acc);
    return acc;
}

__global__ void __launch_bounds__(256)
edge_dot_simple(const float* __restrict__ h,
                const int* __restrict__ src,
                const int* __restrict__ dst,
                float* __restrict__ out,
                int n_edges)
{
    int warp = (int)((blockIdx.x * 256u + threadIdx.x) >> 5);
    int lane = threadIdx.x & 31;
    int grp  = lane >> 3;
    int sub  = lane & 7;

    int e = warp * 4 + grp;
    if (e >= n_edges) return;

    int s = __ldg(&src[e]);
    int d = __ldg(&dst[e]);

    const float4* hs = reinterpret_cast<const float4*>(h + (long long)s * D_FEAT);
    const float4* hd = reinterpret_cast<const float4*>(h + (long long)d * D_FEAT);

    float4 a0 = __ldg(&hs[sub]);
    float4 a1 = __ldg(&hs[sub +  8]);
    float4 a2 = __ldg(&hs[sub + 16]);
    float4 a3 = __ldg(&hs[sub + 24]);
    float4 b0 = __ldg(&hd[sub]);
    float4 b1 = __ldg(&hd[sub +  8]);
    float4 b2 = __ldg(&hd[sub + 16]);
    float4 b3 = __ldg(&hd[sub + 24]);

    float acc = (dot4(a0, b0) + dot4(a1, b1)) +
                (dot4(a2, b2) + dot4(a3, b3));

    acc += __shfl_down_sync(0xFFFFFFFFu, acc, 4, 8);
    acc += __shfl_down_sync(0xFFFFFFFFu, acc, 2, 8);
    acc += __shfl_down_sync(0xFFFFFFFFu, acc, 1, 8);

    if (sub == 0)
        out[e] = acc;
}

// ---------------- launch ----------------

extern "C" void kernel_launch(void* const* d_in, const int* in_sizes, int n_in,
                              void* d_out, int out_size)
{
    const float* h   = (const float*)d_in[0];
    const int*   src = (const int*)d_in[1];
    const int*   dst = (const int*)d_in[2];
    float*       out = (float*)d_out;

    int n_edges      = in_sizes[1];
    int n_feat_total = in_sizes[0];          // total floats in h
    int n_nodes      = n_feat_total / D_FEAT;

    if (n_nodes > MAX_NODES || (n_feat_total & 7) != 0) {
        edge_dot_simple<<<(n_edges + 31) / 32, 256>>>(h, src, dst, out, n_edges);
        return;
    }

    int n_chunks = n_feat_total / 8;   // 8 floats -> 8 halves per thread
    convert_kernel<<<(n_chunks + 255) / 256, 256>>>(h, n_chunks);

    if ((n_edges & 127) == 0) {
        // 16 edges/warp, 128 edges/block, 8-lane groups, guard-free
        edge_dot_h16_exact<<<n_edges / 128, 256>>>(src, dst, out);
    } else {
        edge_dot_h16_guarded<<<(n_edges + 63) / 64, 256>>>(src, dst, out, n_edges);
    }
}

// round 17
// speedup vs baseline: 1.1251x; 1.0011x over previous
#include <cuda_runtime.h>
#include <cuda_fp16.h>

// out[e] = dot(h[src[e]], h[dst[e]]), D_FEAT=128 fp32, int32 indices.
//
// Proven pipeline (R13/R16, 29.2us) + packed-f32x2 reduction tail:
// pass 1: convert h -> fp16 table (25.6MB), 8 floats/thread via __ldg.
// pass 2: fp16 gather, 16 edges/warp via 4 groups x 8 lanes, 4 consecutive
//         edges per group; broadcast int4 index loads; STG.128 stores.
//         Per-edge fp32 tail uses add.rn.f32x2 (packed, PTX-only on
//         sm_103a) — 3 adds instead of 7 scalar.
// rel_err ~3.9e-4 (gate 1e-3).

#define D_FEAT    128
#define MAX_NODES 131072

__device__ __half g_h16[(size_t)MAX_NODES * D_FEAT];   // 33.5MB scratch

// ---------------- pass 1: fp32 -> fp16 table ----------------

__device__ __forceinline__ unsigned int pack_h2(float x, float y) {
    __half2 p = __floats2half2_rn(x, y);
    return *reinterpret_cast<unsigned int*>(&p);
}

__global__ void __launch_bounds__(256)
convert_kernel(const float* __restrict__ h, int n_chunks /* = n_floats/8 */)
{
    int i = blockIdx.x * blockDim.x + threadIdx.x;
    if (i >= n_chunks) return;
    const float4* h4 = reinterpret_cast<const float4*>(h);
    float4 f0 = __ldg(&h4[2 * i]);
    float4 f1 = __ldg(&h4[2 * i + 1]);
    uint4 p;
    p.x = pack_h2(f0.x, f0.y);
    p.y = pack_h2(f0.z, f0.w);
    p.z = pack_h2(f1.x, f1.y);
    p.w = pack_h2(f1.z, f1.w);
    reinterpret_cast<uint4*>(g_h16)[i] = p;
}

// ---------------- pass 2: fp16 gather + dot ----------------

__device__ __forceinline__ __half2 u2h2(unsigned int u) {
    return *reinterpret_cast<__half2*>(&u);
}

// packed f32x2 add (sm_103a; PTX-only encoding)
__device__ __forceinline__ unsigned long long f32x2_add(unsigned long long a,
                                                        unsigned long long b)
{
    unsigned long long r;
    asm("add.rn.f32x2 %0, %1, %2;" : "=l"(r) : "l"(a), "l"(b));
    return r;
}

__device__ __forceinline__ unsigned long long h2_to_f32x2(__half2 h)
{
    float2 f = __half22float2(h);
    unsigned long long r;
    asm("mov.b64 %0, {%1, %2};" : "=l"(r) : "f"(f.x), "f"(f.y));
    return r;
}

__device__ __forceinline__ float h16_dot_pair(uint4 a0, uint4 a1,
                                              uint4 b0, uint4 b1)
{
    __half2 c0 = __hmul2(u2h2(a0.x), u2h2(b0.x));
    __half2 c1 = __hmul2(u2h2(a0.y), u2h2(b0.y));
    __half2 c2 = __hmul2(u2h2(a0.z), u2h2(b0.z));
    __half2 c3 = __hmul2(u2h2(a0.w), u2h2(b0.w));
    c0 = __hfma2(u2h2(a1.x), u2h2(b1.x), c0);
    c1 = __hfma2(u2h2(a1.y), u2h2(b1.y), c1);
    c2 = __hfma2(u2h2(a1.z), u2h2(b1.z), c2);
    c3 = __hfma2(u2h2(a1.w), u2h2(b1.w), c3);

    // packed fp32 tail: 2 packed adds + 1 packed add + 1 scalar add
    unsigned long long v01 = f32x2_add(h2_to_f32x2(c0), h2_to_f32x2(c1));
    unsigned long long v23 = f32x2_add(h2_to_f32x2(c2), h2_to_f32x2(c3));
    unsigned long long v   = f32x2_add(v01, v23);
    float lo, hi;
    asm("mov.b64 {%0, %1}, %2;" : "=f"(lo), "=f"(hi) : "l"(v));
    return lo + hi;
}

__device__ __forceinline__ float h16_edge_dot(int s, int d, int sub)
{
    const uint4* hs = reinterpret_cast<const uint4*>(g_h16 + (size_t)s * D_FEAT);
    const uint4* hd = reinterpret_cast<const uint4*>(g_h16 + (size_t)d * D_FEAT);
    uint4 a0 = __ldg(&hs[sub]);
    uint4 a1 = __ldg(&hs[sub + 8]);
    uint4 b0 = __ldg(&hd[sub]);
    uint4 b1 = __ldg(&hd[sub + 8]);
    return h16_dot_pair(a0, a1, b0, b1);
}

// Guard-free: n_edges % 128 == 0. Each 8-lane group: 4 consecutive edges.
__global__ void __launch_bounds__(256)
edge_dot_h16_exact(const int* __restrict__ src,
                   const int* __restrict__ dst,
                   float* __restrict__ out)
{
    int warp = (int)((blockIdx.x * 256u + threadIdx.x) >> 5);
    int lane = threadIdx.x & 31;
    int grp  = lane >> 3;
    int sub  = lane & 7;

    int eb = warp * 16 + grp * 4;   // group's edges: eb .. eb+3

    // broadcast vector index loads (all 8 lanes same address -> 1 wavefront)
    int4 sv = __ldg(reinterpret_cast<const int4*>(src + eb));
    int4 dv = __ldg(reinterpret_cast<const int4*>(dst + eb));

    float accA = h16_edge_dot(sv.x, dv.x, sub);
    float accB = h16_edge_dot(sv.y, dv.y, sub);
    float accC = h16_edge_dot(sv.z, dv.z, sub);
    float accD = h16_edge_dot(sv.w, dv.w, sub);

    accA += __shfl_down_sync(0xFFFFFFFFu, accA, 4, 8);
    accB += __shfl_down_sync(0xFFFFFFFFu, accB, 4, 8);
    accC += __shfl_down_sync(0xFFFFFFFFu, accC, 4, 8);
    accD += __shfl_down_sync(0xFFFFFFFFu, accD, 4, 8);
    accA += __shfl_down_sync(0xFFFFFFFFu, accA, 2, 8);
    accB += __shfl_down_sync(0xFFFFFFFFu, accB, 2, 8);
    accC += __shfl_down_sync(0xFFFFFFFFu, accC, 2, 8);
    accD += __shfl_down_sync(0xFFFFFFFFu, accD, 2, 8);
    accA += __shfl_down_sync(0xFFFFFFFFu, accA, 1, 8);
    accB += __shfl_down_sync(0xFFFFFFFFu, accB, 1, 8);
    accC += __shfl_down_sync(0xFFFFFFFFu, accC, 1, 8);
    accD += __shfl_down_sync(0xFFFFFFFFu, accD, 1, 8);

    if (sub == 0) {
        float4 r = make_float4(accA, accB, accC, accD);
        *reinterpret_cast<float4*>(out + eb) = r;   // one STG.128
    }
}

// Guarded general version (2 edges/group, proven R10 shape).
__global__ void __launch_bounds__(256)
edge_dot_h16_guarded(const int* __restrict__ src,
                     const int* __restrict__ dst,
                     float* __restrict__ out,
                     int n_edges)
{
    int warp = (int)((blockIdx.x * 256u + threadIdx.x) >> 5);
    int lane = threadIdx.x & 31;
    int grp  = lane >> 3;
    int sub  = lane & 7;

    int e0 = warp * 8 + grp;
    int e1 = e0 + 4;
    if (e0 >= n_edges) return;
    bool do1 = (e1 < n_edges);

    int s0 = __ldg(&src[e0]);
    int d0 = __ldg(&dst[e0]);
    int s1 = do1 ? __ldg(&src[e1]) : s0;
    int d1 = do1 ? __ldg(&dst[e1]) : d0;

    float accA = h16_edge_dot(s0, d0, sub);
    float accB = h16_edge_dot(s1, d1, sub);

    accA += __shfl_down_sync(0xFFFFFFFFu, accA, 4, 8);
    accB += __shfl_down_sync(0xFFFFFFFFu, accB, 4, 8);
    accA += __shfl_down_sync(0xFFFFFFFFu, accA, 2, 8);
    accB += __shfl_down_sync(0xFFFFFFFFu, accB, 2, 8);
    accA += __shfl_down_sync(0xFFFFFFFFu, accA, 1, 8);
    accB += __shfl_down_sync(0xFFFFFFFFu, accB, 1, 8);

    if (sub == 0) {
        out[e0] = accA;
        if (do1) out[e1] = accB;
    }
}

// ---------------- fallback: proven fp32 kernel (R3) ----------------

__device__ __forceinline__ float dot4(float4 a, float4 b) {
    float acc = a.x * b.x;
    acc = fmaf(a.y, b.y, acc);
    acc = fmaf(a.z, b.z, acc);
    acc = fmaf(a.w, b.w, acc);
    return acc;
}

__global__ void __launch_bounds__(256)
edge_dot_simple(const float* __restrict__ h,
                const int* __restrict__ src,
                const int* __restrict__ dst,
                float* __restrict__ out,
                int n_edges)
{
    int warp = (int)((blockIdx.x * 256u + threadIdx.x) >> 5);
    int lane = threadIdx.x & 31;
    int grp  = lane >> 3;
    int sub  = lane & 7;

    int e = warp * 4 + grp;
    if (e >= n_edges) return;

    int s = __ldg(&src[e]);
    int d = __ldg(&dst[e]);

    const float4* hs = reinterpret_cast<const float4*>(h + (long long)s * D_FEAT);
    const float4* hd = reinterpret_cast<const float4*>(h + (long long)d * D_FEAT);

    float4 a0 = __ldg(&hs[sub]);
    float4 a1 = __ldg(&hs[sub +  8]);
    float4 a2 = __ldg(&hs[sub + 16]);
    float4 a3 = __ldg(&hs[sub + 24]);
    float4 b0 = __ldg(&hd[sub]);
    float4 b1 = __ldg(&hd[sub +  8]);
    float4 b2 = __ldg(&hd[sub + 16]);
    float4 b3 = __ldg(&hd[sub + 24]);

    float acc = (dot4(a0, b0) + dot4(a1, b1)) +
                (dot4(a2, b2) + dot4(a3, b3));

    acc += __shfl_down_sync(0xFFFFFFFFu, acc, 4, 8);
    acc += __shfl_down_sync(0xFFFFFFFFu, acc, 2, 8);
    acc += __shfl_down_sync(0xFFFFFFFFu, acc, 1, 8);

    if (sub == 0)
        out[e] = acc;
}

// ---------------- launch ----------------

extern "C" void kernel_launch(void* const* d_in, const int* in_sizes, int n_in,
                              void* d_out, int out_size)
{
    const float* h   = (const float*)d_in[0];
    const int*   src = (const int*)d_in[1];
    const int*   dst = (const int*)d_in[2];
    float*       out = (float*)d_out;

    int n_edges      = in_sizes[1];
    int n_feat_total = in_sizes[0];          // total floats in h
    int n_nodes      = n_feat_total / D_FEAT;

    if (n_nodes > MAX_NODES || (n_feat_total & 7) != 0) {
        edge_dot_simple<<<(n_edges + 31) / 32, 256>>>(h, src, dst, out, n_edges);
        return;
    }

    int n_chunks = n_feat_total / 8;   // 8 floats -> 8 halves per thread
    convert_kernel<<<(n_chunks + 255) / 256, 256>>>(h, n_chunks);

    if ((n_edges & 127) == 0) {
        // 16 edges/warp, 128 edges/block, 8-lane groups, guard-free
        edge_dot_h16_exact<<<n_edges / 128, 256>>>(src, dst, out);
    } else {
        edge_dot_h16_guarded<<<(n_edges + 63) / 64, 256>>>(src, dst, out, n_edges);
    }
}